// round 1
// baseline (speedup 1.0000x reference)
#include <cuda_runtime.h>
#include <cuda_bf16.h>

// Shapes (fixed for this problem)
#define Bn   16
#define Nn   512
#define Rn   10
#define DE   256
#define DR   64
#define DOUT 256
#define INDIM 3200      // (DE+DR)*Rn
#define RELS  320       // DE+DR

// Scratch: v[b,r,o] and Z[b,r,m,o]
__device__ float g_V[Bn * Rn * DOUT];                       // 160*256
__device__ float g_Z[(size_t)Bn * Rn * Nn * DOUT];          // ~84 MB

// ---------------------------------------------------------------------------
// Kernel 1: v[b,r,o] = sum_d rel[b,r,d] * W[o, r*320 + 256 + d]
// grid = B*R blocks, 256 threads (one per o)
// ---------------------------------------------------------------------------
__global__ __launch_bounds__(256) void k_v(const float* __restrict__ rel,
                                           const float* __restrict__ W) {
    const int br = blockIdx.x;          // b*R + r
    const int o  = threadIdx.x;
    const int r  = br % Rn;
    const float* relp = rel + (size_t)br * DR;
    const float* wp   = W + (size_t)o * INDIM + r * RELS + DE;
    float s = 0.f;
#pragma unroll
    for (int d = 0; d < DR; d++) s += relp[d] * wp[d];
    g_V[(size_t)br * DOUT + o] = s;
}

// ---------------------------------------------------------------------------
// Kernel 2: Z[b,r,m,o] = sum_d node[b,m,d] * W[o, r*320 + d]  + v[b,r,o]
// GEMM per (b,r): M=512(m), N=256(o), K=256(d)
// Tiles: BM=128, BN=64, BK=16. 256 threads, TM=8, TN=4.
// grid = (4, 4, B*R)
// ---------------------------------------------------------------------------
__global__ __launch_bounds__(256) void k_z(const float* __restrict__ node,
                                           const float* __restrict__ W) {
    const int br = blockIdx.z;
    const int b  = br / Rn;
    const int r  = br % Rn;
    const int m0 = blockIdx.x * 128;
    const int o0 = blockIdx.y * 64;
    const int t  = threadIdx.x;

    __shared__ float As[16][128];
    __shared__ float Bs[16][64];

    const float* A = node + (size_t)b * Nn * DE;   // [512,256] row-major (m,d)

    const int trow = t / 16;    // 0..15  -> rows trow*8 .. +7
    const int tcol = t % 16;    // 0..15  -> cols tcol*4 .. +3
    float acc[8][4];
#pragma unroll
    for (int i = 0; i < 8; i++)
#pragma unroll
        for (int j = 0; j < 4; j++) acc[i][j] = 0.f;

    const int ar = t / 4;       // 0..63
    const int ac = t % 4;       // 0..3

    for (int k0 = 0; k0 < DE; k0 += 16) {
        // A tile: 128 x 16, transposed store As[k][m]
#pragma unroll
        for (int it = 0; it < 2; it++) {
            const int row = ar + it * 64;
            float4 v4 = *reinterpret_cast<const float4*>(
                &A[(size_t)(m0 + row) * DE + k0 + ac * 4]);
            As[ac * 4 + 0][row] = v4.x;
            As[ac * 4 + 1][row] = v4.y;
            As[ac * 4 + 2][row] = v4.z;
            As[ac * 4 + 3][row] = v4.w;
        }
        // B tile: Bs[d][o] = W[(o0+o)*INDIM + r*320 + k0 + d]   (16 x 64)
        {
            const int o  = t / 4;     // 0..63
            const int dq = t % 4;     // 0..3
            float4 v4 = *reinterpret_cast<const float4*>(
                &W[(size_t)(o0 + o) * INDIM + r * RELS + k0 + dq * 4]);
            Bs[dq * 4 + 0][o] = v4.x;
            Bs[dq * 4 + 1][o] = v4.y;
            Bs[dq * 4 + 2][o] = v4.z;
            Bs[dq * 4 + 3][o] = v4.w;
        }
        __syncthreads();

#pragma unroll
        for (int k = 0; k < 16; k++) {
            float a[8], bb[4];
#pragma unroll
            for (int i = 0; i < 8; i++) a[i] = As[k][trow * 8 + i];
#pragma unroll
            for (int j = 0; j < 4; j++) bb[j] = Bs[k][tcol * 4 + j];
#pragma unroll
            for (int i = 0; i < 8; i++)
#pragma unroll
                for (int j = 0; j < 4; j++) acc[i][j] += a[i] * bb[j];
        }
        __syncthreads();
    }

    // Epilogue: Z = acc + v[b,r,o]
    const float* vp = g_V + (size_t)br * DOUT + o0;
    float* Zp = g_Z + ((size_t)br * Nn + m0) * DOUT + o0;
#pragma unroll
    for (int i = 0; i < 8; i++) {
        const int row = trow * 8 + i;
#pragma unroll
        for (int j = 0; j < 4; j++) {
            Zp[(size_t)row * DOUT + tcol * 4 + j] = acc[i][j] + vp[tcol * 4 + j];
        }
    }
}

// ---------------------------------------------------------------------------
// Kernel 3: out[b,n,o] = bias[o] + sum_r sum_m adj[b,r,n,m] * Z[b,r,m,o]
// GEMM per b: M=512(n), N=256(o), K = R*512 = 5120
// Tiles: BM=128, BN=64, BK=16. 256 threads, TM=8, TN=4.
// grid = (4, 4, B)
// ---------------------------------------------------------------------------
__global__ __launch_bounds__(256) void k_main(const float* __restrict__ adj,
                                              const float* __restrict__ bias,
                                              float* __restrict__ out) {
    const int b  = blockIdx.z;
    const int n0 = blockIdx.x * 128;
    const int o0 = blockIdx.y * 64;
    const int t  = threadIdx.x;

    __shared__ float As[16][128];
    __shared__ float Bs[16][64];

    const int trow = t / 16;
    const int tcol = t % 16;
    float acc[8][4];
#pragma unroll
    for (int i = 0; i < 8; i++)
#pragma unroll
        for (int j = 0; j < 4; j++) acc[i][j] = 0.f;

    const int ar  = t / 4;           // 0..63
    const int ac  = t % 4;           // 0..3
    const int bkr = t / 16;          // 0..15
    const int boc = (t % 16) * 4;    // 0..60

    for (int r = 0; r < Rn; r++) {
        const float* A  = adj + (size_t)(b * Rn + r) * Nn * Nn;        // [512,512]
        const float* Zb = g_Z + (size_t)(b * Rn + r) * Nn * DOUT;      // [512,256]
        for (int k0 = 0; k0 < Nn; k0 += 16) {
            // A tile 128x16 (n,m) contiguous in m; transposed store
#pragma unroll
            for (int it = 0; it < 2; it++) {
                const int row = ar + it * 64;
                float4 v4 = *reinterpret_cast<const float4*>(
                    &A[(size_t)(n0 + row) * Nn + k0 + ac * 4]);
                As[ac * 4 + 0][row] = v4.x;
                As[ac * 4 + 1][row] = v4.y;
                As[ac * 4 + 2][row] = v4.z;
                As[ac * 4 + 3][row] = v4.w;
            }
            // B tile 16x64 from Z, contiguous in o: fully coalesced
            {
                float4 v4 = *reinterpret_cast<const float4*>(
                    &Zb[(size_t)(k0 + bkr) * DOUT + o0 + boc]);
                *reinterpret_cast<float4*>(&Bs[bkr][boc]) = v4;
            }
            __syncthreads();

#pragma unroll
            for (int k = 0; k < 16; k++) {
                float a[8], bb[4];
#pragma unroll
                for (int i = 0; i < 8; i++) a[i] = As[k][trow * 8 + i];
#pragma unroll
                for (int j = 0; j < 4; j++) bb[j] = Bs[k][tcol * 4 + j];
#pragma unroll
                for (int i = 0; i < 8; i++)
#pragma unroll
                    for (int j = 0; j < 4; j++) acc[i][j] += a[i] * bb[j];
            }
            __syncthreads();
        }
    }

    // Epilogue: out = acc + bias
#pragma unroll
    for (int i = 0; i < 8; i++) {
        const int row = trow * 8 + i;
#pragma unroll
        for (int j = 0; j < 4; j++) {
            const int o = o0 + tcol * 4 + j;
            out[((size_t)b * Nn + n0 + row) * DOUT + o] = acc[i][j] + bias[o];
        }
    }
}

// ---------------------------------------------------------------------------
extern "C" void kernel_launch(void* const* d_in, const int* in_sizes, int n_in,
                              void* d_out, int out_size) {
    // Identify inputs by unique element counts (robust to ordering).
    const float *node = nullptr, *rel = nullptr, *adj = nullptr,
                *W = nullptr, *bias = nullptr;
    for (int i = 0; i < n_in; i++) {
        switch (in_sizes[i]) {
            case Bn * Nn * DE:          node = (const float*)d_in[i]; break; // 2097152
            case Bn * Rn * DR:          rel  = (const float*)d_in[i]; break; // 10240
            case Bn * Rn * Nn * Nn / 16 * 16: break;                          // (unused guard)
        }
    }
    // adj / W / bias explicit (distinct sizes)
    for (int i = 0; i < n_in; i++) {
        if (in_sizes[i] == Bn * Rn * Nn * Nn) adj  = (const float*)d_in[i];  // 41943040
        if (in_sizes[i] == DOUT * INDIM)      W    = (const float*)d_in[i];  // 819200
        if (in_sizes[i] == DOUT)              bias = (const float*)d_in[i];  // 256
    }
    float* out = (float*)d_out;

    k_v<<<Bn * Rn, 256>>>(rel, W);
    k_z<<<dim3(Nn / 128, DOUT / 64, Bn * Rn), 256>>>(node, W);
    k_main<<<dim3(Nn / 128, DOUT / 64, Bn), 256>>>(adj, bias, out);
}

// round 3
// speedup vs baseline: 3.2526x; 3.2526x over previous
#include <cuda_runtime.h>
#include <cstdint>

#define Bn   16
#define Nn   512
#define Rn   10
#define DE   256
#define DR   64
#define DOUT 256
#define INDIM 3200
#define RELS  320

// Zt[br][o][m]  (tf32-rounded fp32), 84MB scratch
__device__ float g_Z[(size_t)Bn * Rn * DOUT * Nn];

#define PAD 36                      // floats per smem row (32 data + 4 pad)
#define TILE_FLOATS (128 * PAD)     // one buffer: 128 rows x 36
#define SMEM_FLOATS (4 * TILE_FLOATS + 128)
#define SMEM_BYTES  (SMEM_FLOATS * 4)

// round-to-nearest tf32
__device__ __forceinline__ float rtf32(float x) {
    unsigned u = __float_as_uint(x);
    u = (u + 0x1000u) & 0xFFFFE000u;
    return __uint_as_float(u);
}

__device__ __forceinline__ void mma8(float* c, const uint32_t* a, const uint32_t* b) {
    asm volatile(
        "mma.sync.aligned.m16n8k8.row.col.f32.tf32.tf32.f32 "
        "{%0,%1,%2,%3}, {%4,%5,%6,%7}, {%8,%9}, {%0,%1,%2,%3};"
        : "+f"(c[0]), "+f"(c[1]), "+f"(c[2]), "+f"(c[3])
        : "r"(a[0]), "r"(a[1]), "r"(a[2]), "r"(a[3]), "r"(b[0]), "r"(b[1]));
}

// ---------------------------------------------------------------------------
// Shared mainloop pieces (A rows = M-dim, layout As[row][k]; B rows = N-dim,
// layout Bs[col][k]; both stride PAD). Warp grid 4(M) x 2(N), warp tile 32x64.
// ---------------------------------------------------------------------------
struct Frag { float acc[2][8][4]; };

__device__ __forceinline__ void compute_chunk(const float* __restrict__ As,
                                              const float* __restrict__ Bs,
                                              int wm, int wn, int lane,
                                              float (&acc)[2][8][4]) {
    const float* a_base = As + (wm * 32) * PAD;
    const float* b_base = Bs + (wn * 64) * PAD;
    const int r4 = lane >> 2, c4 = lane & 3;
#pragma unroll
    for (int ks = 0; ks < 4; ks++) {
        const int k = ks * 8 + c4;
        uint32_t af[2][4];
#pragma unroll
        for (int mi = 0; mi < 2; mi++) {
            const float* ap = a_base + (mi * 16 + r4) * PAD + k;
            af[mi][0] = __float_as_uint(ap[0]);
            af[mi][1] = __float_as_uint(ap[8 * PAD]);
            af[mi][2] = __float_as_uint(ap[4]);
            af[mi][3] = __float_as_uint(ap[8 * PAD + 4]);
        }
        uint32_t bf[8][2];
#pragma unroll
        for (int ni = 0; ni < 8; ni++) {
            const float* bp = b_base + (ni * 8 + r4) * PAD + k;
            bf[ni][0] = __float_as_uint(bp[0]);
            bf[ni][1] = __float_as_uint(bp[4]);
        }
#pragma unroll
        for (int mi = 0; mi < 2; mi++)
#pragma unroll
            for (int ni = 0; ni < 8; ni++)
                mma8(acc[mi][ni], af[mi], bf[ni]);
    }
}

// ---------------------------------------------------------------------------
// k_z: per (b,r): Zt[o][m] = rtf32( sum_d W[o, r*320+d]*node[m][d] + v[o] )
// GEMM M=o (tile 128), N=m (tile 128), K=256 (8 chunks)
// grid = (m-tiles 4, o-tiles 2, br 160)
// ---------------------------------------------------------------------------
__global__ __launch_bounds__(256, 1) void k_z(const float* __restrict__ node,
                                              const float* __restrict__ rel,
                                              const float* __restrict__ W) {
    extern __shared__ float sm[];
    float* As = sm;                      // 2 bufs
    float* Bs = sm + 2 * TILE_FLOATS;    // 2 bufs
    float* vs = sm + 4 * TILE_FLOATS;    // 128

    const int tid = threadIdx.x, lane = tid & 31, warp = tid >> 5;
    const int wm = warp & 3, wn = warp >> 2;
    const int br = blockIdx.z, b = br / Rn, r = br - b * Rn;
    const int mm0 = blockIdx.x * 128;    // N-dim offset (m)
    const int o0  = blockIdx.y * 128;    // M-dim offset (o)

    // v[o] = rel . W_rel_r[o]
    if (tid < 128) {
        const float* wr = W + (size_t)(o0 + tid) * INDIM + r * RELS + DE;
        const float* rp = rel + (size_t)br * DR;
        float s = 0.f;
#pragma unroll
        for (int d = 0; d < DR; d++) s += rp[d] * wr[d];
        vs[tid] = s;
    }

    const int lrow = tid >> 3, lq = (tid & 7) * 4;
    const float* Abase = W + (size_t)o0 * INDIM + r * RELS;       // rows o, stride INDIM
    const float* Bbase = node + (size_t)b * Nn * DE + (size_t)mm0 * DE;  // rows m, stride DE

    float acc[2][8][4];
#pragma unroll
    for (int mi = 0; mi < 2; mi++)
#pragma unroll
        for (int ni = 0; ni < 8; ni++)
#pragma unroll
            for (int q = 0; q < 4; q++) acc[mi][ni][q] = 0.f;

    float4 va[4], vb[4];
    auto ldg = [&](int j) {
#pragma unroll
        for (int i = 0; i < 4; i++) {
            const int row = i * 32 + lrow;
            va[i] = *reinterpret_cast<const float4*>(Abase + (size_t)row * INDIM + j * 32 + lq);
            vb[i] = *reinterpret_cast<const float4*>(Bbase + (size_t)row * DE + j * 32 + lq);
        }
    };
    auto sts = [&](int buf) {
        float* ad = As + buf * TILE_FLOATS;
        float* bd = Bs + buf * TILE_FLOATS;
#pragma unroll
        for (int i = 0; i < 4; i++) {
            const int row = i * 32 + lrow;
            float4 a = va[i], bq = vb[i];
            a.x = rtf32(a.x); a.y = rtf32(a.y); a.z = rtf32(a.z); a.w = rtf32(a.w);
            bq.x = rtf32(bq.x); bq.y = rtf32(bq.y); bq.z = rtf32(bq.z); bq.w = rtf32(bq.w);
            *reinterpret_cast<float4*>(ad + row * PAD + lq) = a;
            *reinterpret_cast<float4*>(bd + row * PAD + lq) = bq;
        }
    };

    ldg(0); sts(0); __syncthreads();
    const int J = 8;
    for (int j = 0; j < J; j++) {
        if (j + 1 < J) ldg(j + 1);
        compute_chunk(As + (j & 1) * TILE_FLOATS, Bs + (j & 1) * TILE_FLOATS,
                      wm, wn, lane, acc);
        __syncthreads();
        if (j + 1 < J) { sts((j + 1) & 1); __syncthreads(); }
    }

    // Epilogue: rows = o, cols = m.  Zt[o][m] float2 stores.
    const int r4 = lane >> 2, c2 = 2 * (lane & 3);
#pragma unroll
    for (int mi = 0; mi < 2; mi++) {
#pragma unroll
        for (int ni = 0; ni < 8; ni++) {
            const int orow = wm * 32 + mi * 16 + r4;
            const int mcol = wn * 64 + ni * 8 + c2;
            float* zp = g_Z + (size_t)br * (DOUT * Nn) + (size_t)(o0 + orow) * Nn + mm0 + mcol;
            float v0 = vs[orow];
            float2 lo = { rtf32(acc[mi][ni][0] + v0), rtf32(acc[mi][ni][1] + v0) };
            *reinterpret_cast<float2*>(zp) = lo;
            float v1 = vs[orow + 8];
            float2 hi = { rtf32(acc[mi][ni][2] + v1), rtf32(acc[mi][ni][3] + v1) };
            *reinterpret_cast<float2*>(zp + (size_t)8 * Nn) = hi;
        }
    }
}

// ---------------------------------------------------------------------------
// k_main: per b: out[n][o] = bias[o] + sum_{r,m} adj[b,r,n,m] * Zt[br][o][m]
// GEMM M=n (tile 128), N=o (tile 128), K=5120 (160 chunks: r=j>>4, kk=j&15)
// grid = (n-tiles 4, o-tiles 2, b 16)
// ---------------------------------------------------------------------------
__global__ __launch_bounds__(256, 1) void k_main(const float* __restrict__ adj,
                                                 const float* __restrict__ bias,
                                                 float* __restrict__ out) {
    extern __shared__ float sm[];
    float* As = sm;
    float* Bs = sm + 2 * TILE_FLOATS;
    float* bsm = sm + 4 * TILE_FLOATS;

    const int tid = threadIdx.x, lane = tid & 31, warp = tid >> 5;
    const int wm = warp & 3, wn = warp >> 2;
    const int b = blockIdx.z;
    const int n0 = blockIdx.x * 128, o0 = blockIdx.y * 128;

    if (tid < 128) bsm[tid] = bias[o0 + tid];

    const int lrow = tid >> 3, lq = (tid & 7) * 4;

    float acc[2][8][4];
#pragma unroll
    for (int mi = 0; mi < 2; mi++)
#pragma unroll
        for (int ni = 0; ni < 8; ni++)
#pragma unroll
            for (int q = 0; q < 4; q++) acc[mi][ni][q] = 0.f;

    float4 va[4], vb[4];
    auto ldg = [&](int j) {
        const int r = j >> 4, kk = j & 15;
        const float* Ab = adj + (size_t)(b * Rn + r) * (Nn * Nn) + (size_t)n0 * Nn + kk * 32;
        const float* Bb = g_Z + (size_t)(b * Rn + r) * (DOUT * Nn) + (size_t)o0 * Nn + kk * 32;
#pragma unroll
        for (int i = 0; i < 4; i++) {
            const int row = i * 32 + lrow;
            va[i] = *reinterpret_cast<const float4*>(Ab + (size_t)row * Nn + lq);
            vb[i] = *reinterpret_cast<const float4*>(Bb + (size_t)row * Nn + lq);
        }
    };
    auto sts = [&](int buf) {
        float* ad = As + buf * TILE_FLOATS;
        float* bd = Bs + buf * TILE_FLOATS;
#pragma unroll
        for (int i = 0; i < 4; i++) {
            const int row = i * 32 + lrow;
            float4 a = va[i];
            a.x = rtf32(a.x); a.y = rtf32(a.y); a.z = rtf32(a.z); a.w = rtf32(a.w);
            *reinterpret_cast<float4*>(ad + row * PAD + lq) = a;
            *reinterpret_cast<float4*>(bd + row * PAD + lq) = vb[i];   // Zt pre-rounded
        }
    };

    ldg(0); sts(0); __syncthreads();
    const int J = 160;
    for (int j = 0; j < J; j++) {
        if (j + 1 < J) ldg(j + 1);
        compute_chunk(As + (j & 1) * TILE_FLOATS, Bs + (j & 1) * TILE_FLOATS,
                      wm, wn, lane, acc);
        __syncthreads();
        if (j + 1 < J) { sts((j + 1) & 1); __syncthreads(); }
    }

    // Epilogue: rows = n, cols = o.
    const int r4 = lane >> 2, c2 = 2 * (lane & 3);
#pragma unroll
    for (int mi = 0; mi < 2; mi++) {
#pragma unroll
        for (int ni = 0; ni < 8; ni++) {
            const int nrow = wm * 32 + mi * 16 + r4;
            const int ocol = wn * 64 + ni * 8 + c2;
            float* op = out + ((size_t)(b * Nn + n0 + nrow)) * DOUT + o0 + ocol;
            float2 lo = { acc[mi][ni][0] + bsm[ocol], acc[mi][ni][1] + bsm[ocol + 1] };
            *reinterpret_cast<float2*>(op) = lo;
            float2 hi = { acc[mi][ni][2] + bsm[ocol], acc[mi][ni][3] + bsm[ocol + 1] };
            *reinterpret_cast<float2*>(op + (size_t)8 * DOUT) = hi;
        }
    }
}

// ---------------------------------------------------------------------------
extern "C" void kernel_launch(void* const* d_in, const int* in_sizes, int n_in,
                              void* d_out, int out_size) {
    const float *node = nullptr, *rel = nullptr, *adj = nullptr,
                *W = nullptr, *bias = nullptr;
    for (int i = 0; i < n_in; i++) {
        const int s = in_sizes[i];
        if      (s == Bn * Nn * DE)      node = (const float*)d_in[i];
        else if (s == Bn * Rn * DR)      rel  = (const float*)d_in[i];
        else if (s == Bn * Rn * Nn * Nn) adj  = (const float*)d_in[i];
        else if (s == DOUT * INDIM)      W    = (const float*)d_in[i];
        else if (s == DOUT)              bias = (const float*)d_in[i];
    }
    cudaFuncSetAttribute(k_z,    cudaFuncAttributeMaxDynamicSharedMemorySize, SMEM_BYTES);
    cudaFuncSetAttribute(k_main, cudaFuncAttributeMaxDynamicSharedMemorySize, SMEM_BYTES);

    k_z   <<<dim3(4, 2, Bn * Rn), 256, SMEM_BYTES>>>(node, rel, W);
    k_main<<<dim3(4, 2, Bn),      256, SMEM_BYTES>>>(adj, bias, (float*)d_out);
}